// round 1
// baseline (speedup 1.0000x reference)
#include <cuda_runtime.h>
#include <cuda_bf16.h>

#define N_ITEMS 20000
#define ALPHA 0.2f
#define NEG_INF_V -9000000000000000.0f

// Precomputed W@a1 and W@a2 (64 floats each) — scratch via __device__ globals
// (no allocation allowed in kernel_launch).
__device__ float g_wa1[64];
__device__ float g_wa2[64];

__global__ void precompute_wa(const float* __restrict__ W, const float* __restrict__ a) {
    int f = threadIdx.x;  // 0..63
    float s1 = 0.f, s2 = 0.f;
#pragma unroll
    for (int h = 0; h < 64; ++h) {
        float w = W[f * 64 + h];
        s1 += w * a[h];
        s2 += w * a[64 + h];
    }
    g_wa1[f] = s1;
    g_wa2[f] = s2;
}

__global__ __launch_bounds__(256, 4) void gat_kernel(
    const float* __restrict__ item,
    const float* __restrict__ ent,
    const int*   __restrict__ adj,
    float*       __restrict__ out)
{
    // 64 rows (m) x 64 cols (f), row stride padded to 68 floats to avoid
    // bank conflicts in the per-m dot phase while keeping 16B alignment.
    __shared__ float tile[64 * 68];
    __shared__ float wa2s[64];
    __shared__ float dbuf[64];   // entity[m] . wa2
    __shared__ float att[64];    // softmax attention
    __shared__ float part[4 * 64];

    const int n = blockIdx.x;
    const int t = threadIdx.x;
    const float* eb = ent + (size_t)n * 4096;

    if (t < 64) wa2s[t] = g_wa2[t];

    // --- Phase 0: coalesced tile load (warp reads 512B contiguous per instr) ---
#pragma unroll
    for (int k = 0; k < 4; ++k) {
        int e = k * 1024 + t * 4;
        int m = e >> 6, f = e & 63;
        float4 v = *reinterpret_cast<const float4*>(eb + e);
        *reinterpret_cast<float4*>(&tile[m * 68 + f]) = v;
    }
    __syncthreads();

    // --- Phase 1: d[m] = entity[n,m,:] . wa2  (64 groups x 4 lanes) ---
    {
        int g = t >> 2, l = t & 3;
        const float* row = &tile[g * 68 + l * 16];
        const float* w   = &wa2s[l * 16];
        float acc = 0.f;
#pragma unroll
        for (int i = 0; i < 16; ++i) acc = fmaf(row[i], w[i], acc);
        acc += __shfl_xor_sync(0xffffffffu, acc, 1);
        acc += __shfl_xor_sync(0xffffffffu, acc, 2);
        if (l == 0) dbuf[g] = acc;
    }
    __syncthreads();

    // --- Phase 2: warp 0 computes s1 and masked softmax over m ---
    if (t < 32) {
        // s1 = item[n] . wa1 (64 elems, 2 per lane)
        float p = item[(size_t)n * 64 + t]      * g_wa1[t]
                + item[(size_t)n * 64 + t + 32] * g_wa1[t + 32];
#pragma unroll
        for (int o = 16; o > 0; o >>= 1) p += __shfl_xor_sync(0xffffffffu, p, o);
        const float s1 = p;

        float e0 = s1 + dbuf[t];
        float e1 = s1 + dbuf[t + 32];
        e0 = e0 > 0.f ? e0 : ALPHA * e0;
        e1 = e1 > 0.f ? e1 : ALPHA * e1;
        const int a0 = adj[(size_t)n * 64 + t];
        const int a1 = adj[(size_t)n * 64 + t + 32];
        if (a0 <= 0) e0 = NEG_INF_V;
        if (a1 <= 0) e1 = NEG_INF_V;

        float mx = fmaxf(e0, e1);
#pragma unroll
        for (int o = 16; o > 0; o >>= 1) mx = fmaxf(mx, __shfl_xor_sync(0xffffffffu, mx, o));
        const float x0 = __expf(e0 - mx);
        const float x1 = __expf(e1 - mx);
        float sm = x0 + x1;
#pragma unroll
        for (int o = 16; o > 0; o >>= 1) sm += __shfl_xor_sync(0xffffffffu, sm, o);
        const float inv = 1.0f / sm;
        att[t]      = x0 * inv;
        att[t + 32] = x1 * inv;
    }
    __syncthreads();

    // --- Phase 3: out[f] = sum_m att[m] * entity[m,f]  (f-contiguous, conflict-free) ---
    {
        int f = t & 63, c = t >> 6;
        float acc = 0.f;
#pragma unroll
        for (int i = 0; i < 16; ++i) {
            int m = c * 16 + i;
            acc = fmaf(att[m], tile[m * 68 + f], acc);
        }
        part[c * 64 + f] = acc;
    }
    __syncthreads();

    if (t < 64) {
        float r = part[t] + part[64 + t] + part[128 + t] + part[192 + t]
                + item[(size_t)n * 64 + t];
        out[(size_t)n * 64 + t] = r;
    }
}

extern "C" void kernel_launch(void* const* d_in, const int* in_sizes, int n_in,
                              void* d_out, int out_size) {
    const float* item = (const float*)d_in[0];
    const float* ent  = (const float*)d_in[1];
    const int*   adj  = (const int*)d_in[2];
    const float* W    = (const float*)d_in[3];
    const float* a    = (const float*)d_in[4];
    float* out = (float*)d_out;

    precompute_wa<<<1, 64>>>(W, a);
    gat_kernel<<<N_ITEMS, 256>>>(item, ent, adj, out);
}

// round 2
// speedup vs baseline: 1.6009x; 1.6009x over previous
#include <cuda_runtime.h>
#include <cuda_bf16.h>

#define N_ITEMS 20000
#define ALPHA 0.2f
#define NEG_INF_V -9000000000000000.0f

// Precomputed W@a1 and W@a2 (64 floats each).
__device__ float g_wa1[64];
__device__ float g_wa2[64];

__global__ void precompute_wa(const float* __restrict__ W, const float* __restrict__ a) {
    int f = threadIdx.x;  // 0..63
    float s1 = 0.f, s2 = 0.f;
#pragma unroll
    for (int h = 0; h < 64; ++h) {
        float w = W[f * 64 + h];
        s1 += w * a[h];
        s2 += w * a[64 + h];
    }
    g_wa1[f] = s1;
    g_wa2[f] = s2;
}

// One CTA per item row n. Entity tile (64x64 f32 = 16KB) is REGISTER-resident:
// thread t holds 4 float4s: element range f=(t&15)*4..+3 of rows
// m = k*16 + (t>>4), k=0..3. No SMEM staging of the tile at all.
__global__ __launch_bounds__(256) void gat_kernel(
    const float* __restrict__ item,
    const float* __restrict__ ent,
    const int*   __restrict__ adj,
    float*       __restrict__ out)
{
    __shared__ float dbuf[64];     // entity[m] . wa2
    __shared__ float att[64];      // softmax attention
    __shared__ float part[8 * 64]; // per-warp output partials

    const int n = blockIdx.x;
    const int t = threadIdx.x;
    const int grp = t >> 4;        // 0..15 (16-lane group id)
    const int sub = t & 15;        // 0..15 position in group
    const float* eb = ent + (size_t)n * 4096;

    // wa2 chunk for this thread's f-range (f = sub*4 .. +3)
    const float4 w2 = *reinterpret_cast<const float4*>(&g_wa2[sub * 4]);

    // --- Load tile into registers + inline dot with wa2 ---
    float4 v[4];
    float d[4];
#pragma unroll
    for (int k = 0; k < 4; ++k) {
        v[k] = *reinterpret_cast<const float4*>(eb + k * 1024 + t * 4);
    }
#pragma unroll
    for (int k = 0; k < 4; ++k) {
        d[k] = v[k].x * w2.x + v[k].y * w2.y + v[k].z * w2.z + v[k].w * w2.w;
    }
    // Reduce over the 16 lanes sharing each m (xor offsets <16 stay in group)
#pragma unroll
    for (int o = 1; o < 16; o <<= 1) {
#pragma unroll
        for (int k = 0; k < 4; ++k)
            d[k] += __shfl_xor_sync(0xffffffffu, d[k], o);
    }
    if (sub == 0) {
#pragma unroll
        for (int k = 0; k < 4; ++k)
            dbuf[k * 16 + grp] = d[k];
    }
    __syncthreads();

    // --- Warp 0: s1 = item.wa1, then masked leaky-relu softmax over m ---
    if (t < 32) {
        float p = item[(size_t)n * 64 + t]      * g_wa1[t]
                + item[(size_t)n * 64 + t + 32] * g_wa1[t + 32];
#pragma unroll
        for (int o = 16; o > 0; o >>= 1) p += __shfl_xor_sync(0xffffffffu, p, o);
        const float s1 = p;

        float e0 = s1 + dbuf[t];
        float e1 = s1 + dbuf[t + 32];
        e0 = e0 > 0.f ? e0 : ALPHA * e0;
        e1 = e1 > 0.f ? e1 : ALPHA * e1;
        if (adj[(size_t)n * 64 + t]      <= 0) e0 = NEG_INF_V;
        if (adj[(size_t)n * 64 + t + 32] <= 0) e1 = NEG_INF_V;

        float mx = fmaxf(e0, e1);
#pragma unroll
        for (int o = 16; o > 0; o >>= 1) mx = fmaxf(mx, __shfl_xor_sync(0xffffffffu, mx, o));
        const float x0 = __expf(e0 - mx);
        const float x1 = __expf(e1 - mx);
        float sm = x0 + x1;
#pragma unroll
        for (int o = 16; o > 0; o >>= 1) sm += __shfl_xor_sync(0xffffffffu, sm, o);
        const float inv = 1.0f / sm;
        att[t]      = x0 * inv;
        att[t + 32] = x1 * inv;
    }
    __syncthreads();

    // --- Weighted sum from registers: acc[f] += att[m_k] * v[k] ---
    float4 acc = make_float4(0.f, 0.f, 0.f, 0.f);
#pragma unroll
    for (int k = 0; k < 4; ++k) {
        const float a_m = att[k * 16 + grp];   // broadcast within 16-lane group
        acc.x = fmaf(a_m, v[k].x, acc.x);
        acc.y = fmaf(a_m, v[k].y, acc.y);
        acc.z = fmaf(a_m, v[k].z, acc.z);
        acc.w = fmaf(a_m, v[k].w, acc.w);
    }
    // Combine the two 16-lane groups in each warp (same f-range, different m)
    acc.x += __shfl_xor_sync(0xffffffffu, acc.x, 16);
    acc.y += __shfl_xor_sync(0xffffffffu, acc.y, 16);
    acc.z += __shfl_xor_sync(0xffffffffu, acc.z, 16);
    acc.w += __shfl_xor_sync(0xffffffffu, acc.w, 16);

    const int w = t >> 5;
    if ((t & 31) < 16) {
        *reinterpret_cast<float4*>(&part[w * 64 + sub * 4]) = acc;
    }
    __syncthreads();

    // --- Final: reduce 8 warp partials + residual, store ---
    if (t < 64) {
        float r = part[t]       + part[64 + t]  + part[128 + t] + part[192 + t]
                + part[256 + t] + part[320 + t] + part[384 + t] + part[448 + t]
                + item[(size_t)n * 64 + t];
        out[(size_t)n * 64 + t] = r;
    }
}

extern "C" void kernel_launch(void* const* d_in, const int* in_sizes, int n_in,
                              void* d_out, int out_size) {
    const float* item = (const float*)d_in[0];
    const float* ent  = (const float*)d_in[1];
    const int*   adj  = (const int*)d_in[2];
    const float* W    = (const float*)d_in[3];
    const float* a    = (const float*)d_in[4];
    float* out = (float*)d_out;

    precompute_wa<<<1, 64>>>(W, a);
    gat_kernel<<<N_ITEMS, 256>>>(item, ent, adj, out);
}

// round 3
// speedup vs baseline: 1.7619x; 1.1006x over previous
#include <cuda_runtime.h>
#include <cuda_bf16.h>

#define N_ITEMS 20000
#define ALPHA 0.2f
#define NEG_INF_V -9000000000000000.0f

__device__ float g_wa1[64];
__device__ float g_wa2[64];

__global__ void precompute_wa(const float* __restrict__ W, const float* __restrict__ a) {
    int f = threadIdx.x;  // 0..63
    float s1 = 0.f, s2 = 0.f;
#pragma unroll
    for (int h = 0; h < 64; ++h) {
        float w = W[f * 64 + h];
        s1 += w * a[h];
        s2 += w * a[64 + h];
    }
    g_wa1[f] = s1;
    g_wa2[f] = s2;
}

// One CTA per item row n. Entity tile register-resident (thread t holds
// f-range (t&15)*4..+3 of rows m = k*16 + (t>>4), k=0..3).
// Softmax is replicated in every warp (registers only) -> 2 barriers total,
// no serialized single-warp phase, item/adj prefetched before tile loads.
__global__ __launch_bounds__(256, 6) void gat_kernel(
    const float* __restrict__ item,
    const float* __restrict__ ent,
    const int*   __restrict__ adj,
    float*       __restrict__ out)
{
    __shared__ float dbuf[64];     // entity[m] . wa2
    __shared__ float part[8 * 64]; // per-warp output partials

    const int n    = blockIdx.x;
    const int t    = threadIdx.x;
    const int lane = t & 31;
    const int sub  = t & 15;       // f-chunk id
    const int grpG = t >> 4;       // 0..15 global group (m low bits)
    const int w    = t >> 5;       // warp id
    const float* eb = ent + (size_t)n * 4096;

    // --- Prefetch (per-warp redundant; L1 hits after first warp) ---
    const float it0 = item[(size_t)n * 64 + lane];
    const float it1 = item[(size_t)n * 64 + 32 + lane];
    const int   ja0 = adj[(size_t)n * 64 + lane];
    const int   ja1 = adj[(size_t)n * 64 + 32 + lane];

    const float4 w2 = *reinterpret_cast<const float4*>(&g_wa2[sub * 4]);

    // --- Entity tile loads (4x LDG.128 per thread, front-batched) ---
    float4 v[4];
#pragma unroll
    for (int k = 0; k < 4; ++k)
        v[k] = *reinterpret_cast<const float4*>(eb + k * 1024 + t * 4);

    // s1 = item[n].wa1, computed per-warp while tile loads are in flight
    float p = it0 * g_wa1[lane] + it1 * g_wa1[32 + lane];
#pragma unroll
    for (int o = 16; o > 0; o >>= 1) p += __shfl_xor_sync(0xffffffffu, p, o);
    const float s1 = p;

    // --- d[m] = entity[m].wa2 ---
    float d[4];
#pragma unroll
    for (int k = 0; k < 4; ++k)
        d[k] = v[k].x * w2.x + v[k].y * w2.y + v[k].z * w2.z + v[k].w * w2.w;
#pragma unroll
    for (int o = 1; o < 16; o <<= 1) {
#pragma unroll
        for (int k = 0; k < 4; ++k)
            d[k] += __shfl_xor_sync(0xffffffffu, d[k], o);
    }
    if (sub == 0) {
#pragma unroll
        for (int k = 0; k < 4; ++k)
            dbuf[k * 16 + (grpG)] = d[k];
    }
    __syncthreads();

    // --- Softmax, replicated in every warp (registers only) ---
    float e0 = s1 + dbuf[lane];
    float e1 = s1 + dbuf[32 + lane];
    e0 = e0 > 0.f ? e0 : ALPHA * e0;
    e1 = e1 > 0.f ? e1 : ALPHA * e1;
    if (ja0 <= 0) e0 = NEG_INF_V;
    if (ja1 <= 0) e1 = NEG_INF_V;

    float mx = fmaxf(e0, e1);
#pragma unroll
    for (int o = 16; o > 0; o >>= 1) mx = fmaxf(mx, __shfl_xor_sync(0xffffffffu, mx, o));
    const float x0 = __expf(e0 - mx);
    const float x1 = __expf(e1 - mx);
    float sm = x0 + x1;
#pragma unroll
    for (int o = 16; o > 0; o >>= 1) sm += __shfl_xor_sync(0xffffffffu, sm, o);
    const float inv  = 1.0f / sm;
    const float att0 = x0 * inv;   // lane holds att[m=lane]
    const float att1 = x1 * inv;   // lane holds att[m=lane+32]

    // Attention values this thread needs: m = k*16 + grpG, k=0..3
    float am[4];
    am[0] = __shfl_sync(0xffffffffu, att0, grpG);
    am[1] = __shfl_sync(0xffffffffu, att0, 16 + grpG);
    am[2] = __shfl_sync(0xffffffffu, att1, grpG);
    am[3] = __shfl_sync(0xffffffffu, att1, 16 + grpG);

    // --- Weighted sum from registers ---
    float4 acc = make_float4(0.f, 0.f, 0.f, 0.f);
#pragma unroll
    for (int k = 0; k < 4; ++k) {
        acc.x = fmaf(am[k], v[k].x, acc.x);
        acc.y = fmaf(am[k], v[k].y, acc.y);
        acc.z = fmaf(am[k], v[k].z, acc.z);
        acc.w = fmaf(am[k], v[k].w, acc.w);
    }
    acc.x += __shfl_xor_sync(0xffffffffu, acc.x, 16);
    acc.y += __shfl_xor_sync(0xffffffffu, acc.y, 16);
    acc.z += __shfl_xor_sync(0xffffffffu, acc.z, 16);
    acc.w += __shfl_xor_sync(0xffffffffu, acc.w, 16);

    if (lane < 16)
        *reinterpret_cast<float4*>(&part[w * 64 + sub * 4]) = acc;
    __syncthreads();

    // --- Final: reduce 8 warp partials + residual (item is L1-hot) ---
    if (t < 64) {
        float r = part[t]       + part[64 + t]  + part[128 + t] + part[192 + t]
                + part[256 + t] + part[320 + t] + part[384 + t] + part[448 + t]
                + item[(size_t)n * 64 + t];
        out[(size_t)n * 64 + t] = r;
    }
}

extern "C" void kernel_launch(void* const* d_in, const int* in_sizes, int n_in,
                              void* d_out, int out_size) {
    const float* item = (const float*)d_in[0];
    const float* ent  = (const float*)d_in[1];
    const int*   adj  = (const int*)d_in[2];
    const float* W    = (const float*)d_in[3];
    const float* a    = (const float*)d_in[4];
    float* out = (float*)d_out;

    precompute_wa<<<1, 64>>>(W, a);
    gat_kernel<<<N_ITEMS, 256>>>(item, ent, adj, out);
}